// round 15
// baseline (speedup 1.0000x reference)
#include <cuda_runtime.h>
#include <cstdint>

// RoIBridge round 15 (= R14 retry; R14 hit broker infra failure, never ran).
// TMA bulk stores with a DEEP pipeline:
//  - 4 staging buffers (32KB smem), cp.async.bulk.wait_group.read 3 ->
//    buffer-reuse stalls eliminated (R13's 2-buffer version serialized)
//  - table gathered via __ldg from L1 (57.6KB fits carveout; smem only 32KB);
//    L1TEX carries ONLY the gather stream, stores bypass LSU/L1TEX entirely
//  - per iteration: warp-uniform obj/frac LDGs (prefetched one tile ahead),
//    conditional L1 gathers, STS to staging, fence+bar, single-thread 8KB
//    cp.async.bulk store
// Rationale: STG.128 costs ~12 LSU cyc/512B -> ~6.5KB/cyc chip ceiling shared
// with all LSU work = the stubborn ~47us plateau. TMA stores skip that pipe.

static constexpr int IMAGE_SIZE = 224;
static constexpr int ROWS = 2048 * 128;          // 262144
static constexpr int TILE_ROWS = 8;
static constexpr int NTILES = ROWS / TILE_ROWS;  // 32768
static constexpr int TILE_F4 = TILE_ROWS * 64;   // 512 float4 = 8192 B
static constexpr int TILE_BYTES = TILE_F4 * 16;
static constexpr int NBUF = 4;

__device__ __forceinline__ int clamp_idx(float f) {
    float x = fminf(fmaxf(f * (float)IMAGE_SIZE, 0.0f), (float)IMAGE_SIZE);
    return (int)x;   // trunc toward zero == astype(int32), x >= 0
}

extern __shared__ float4 s_stage[];   // [NBUF][TILE_F4] = 32768 B

__global__ void __launch_bounds__(512, 3)
roibridge_kernel(const float4* __restrict__ frac4,   // [ROWS]
                 const int*    __restrict__ obj,     // [ROWS]
                 const float4* __restrict__ table4,  // [225*16]
                 float4*       __restrict__ out)     // [ROWS*64]
{
    const int tid_in = threadIdx.x;
    const int rsub   = tid_in >> 6;      // row within tile 0..7
    const int d4     = tid_in & 63;      // float4 within row
    const int c      = d4 >> 4;          // coordinate 0..3
    const int dd     = d4 & 15;          // float4 lane within coord embedding

    uint32_t stage_addr0;
    asm("{ .reg .u64 t; cvta.to.shared.u64 t, %1; cvt.u32.u64 %0, t; }"
        : "=r"(stage_addr0) : "l"((void*)s_stage));

    const float4 z = make_float4(0.f, 0.f, 0.f, 0.f);

    // ---- prologue: scalar loads for first tile ----
    int t = blockIdx.x;
    int    o = 0;
    float4 f = z;
    if (t < NTILES) {
        int row = t * TILE_ROWS + rsub;
        o = __ldg(obj + row);
        f = __ldg(frac4 + row);
    }

    int it = 0;
    for (; t < NTILES; t += gridDim.x, ++it) {
        const int buf = it & (NBUF - 1);

        // ---- allow at most NBUF-1 unread store groups, then sync so no
        //      thread overwrites a buffer TMA may still be reading ----
        if (tid_in == 0)
            asm volatile("cp.async.bulk.wait_group.read %0;"
                         :: "n"(NBUF - 1) : "memory");
        __syncthreads();

        // ---- gather this thread's float4 from L1-resident table ----
        float4 v = z;
        if (o == 1) {
            float fc = (c == 0) ? f.x : (c == 1) ? f.y : (c == 2) ? f.z : f.w;
            v = __ldg(table4 + clamp_idx(fc) * 16 + dd);
        }
        s_stage[buf * TILE_F4 + tid_in] = v;

        // ---- prefetch next tile's scalars (overlap with fence/bar/TMA) ----
        const int tn = t + gridDim.x;
        if (tn < NTILES) {
            int row = tn * TILE_ROWS + rsub;
            o = __ldg(obj + row);
            f = __ldg(frac4 + row);
        }

        // ---- order STS before async-proxy read, then 8KB bulk store ----
        asm volatile("fence.proxy.async.shared::cta;" ::: "memory");
        __syncthreads();
        if (tid_in == 0) {
            const float4* gdst = out + (size_t)t * TILE_F4;
            uint32_t saddr = stage_addr0 + buf * TILE_BYTES;
            asm volatile(
                "cp.async.bulk.global.shared::cta.bulk_group [%0], [%1], %2;"
                :: "l"(gdst), "r"(saddr), "r"((int)TILE_BYTES) : "memory");
            asm volatile("cp.async.bulk.commit_group;" ::: "memory");
        }
    }

    // ---- drain all outstanding bulk stores before exit ----
    if (tid_in == 0)
        asm volatile("cp.async.bulk.wait_group 0;" ::: "memory");
}

extern "C" void kernel_launch(void* const* d_in, const int* in_sizes, int n_in,
                              void* d_out, int out_size)
{
    const float4* frac4 = (const float4*)d_in[0];   // [2048,128,4] f32
    const int*    obj   = (const int*)d_in[1];      // [2048,128] i32
    const float4* table = (const float4*)d_in[2];   // [225,64] f32
    float4* out = (float4*)d_out;

    const int smem_bytes = NBUF * TILE_BYTES;       // 32768
    cudaFuncSetAttribute(roibridge_kernel,
                         cudaFuncAttributeMaxDynamicSharedMemorySize, smem_bytes);

    const int threads = 512;
    const int blocks = 152 * 3;   // 152 SMs, 3 blocks/SM

    roibridge_kernel<<<blocks, threads, smem_bytes>>>(frac4, obj, table, out);
}

// round 16
// speedup vs baseline: 1.4193x; 1.4193x over previous
#include <cuda_runtime.h>
#include <cstdint>

// RoIBridge round 16: 256-bit stores (st.global.v8.f32, sm_100a/103a).
// TMA store path falsified twice (barrier tax > LSU savings). Attack the
// LSU store-issue cost directly instead: thread = (row, j 0..7); per coord
// 2x LDS.128 gather + ONE STG.256 -> store instruction count halves vs R10
// while LDS/LDG counts stay flat. Same shell: 57.6KB smem table,
// 456 blocks x 512 threads, 3 blocks/SM, conditional gathers.

static constexpr int IMAGE_SIZE = 224;
static constexpr int ROWS = 2048 * 128;       // 262144
static constexpr int TABLE_F4 = 225 * 16;     // 3600 float4 = 57600 B
static constexpr int WORK = ROWS * 8;         // 2,097,152 items (8 lanes/row)

__device__ __forceinline__ int clamp_idx(float f) {
    float x = fminf(fmaxf(f * (float)IMAGE_SIZE, 0.0f), (float)IMAGE_SIZE);
    return (int)x;   // trunc toward zero == astype(int32), x >= 0
}

// 256-bit store: two float4 to one 32B-aligned address, single instruction.
__device__ __forceinline__ void st256(float4* p, float4 a, float4 b) {
    asm volatile(
        "st.global.v8.f32 [%0], {%1,%2,%3,%4,%5,%6,%7,%8};"
        :: "l"(p),
           "f"(a.x), "f"(a.y), "f"(a.z), "f"(a.w),
           "f"(b.x), "f"(b.y), "f"(b.z), "f"(b.w)
        : "memory");
}

extern __shared__ float4 s_tab[];             // [225*16]

__global__ void __launch_bounds__(512, 3)
roibridge_kernel(const float4* __restrict__ frac4,   // [ROWS]
                 const int*    __restrict__ obj,     // [ROWS]
                 const float4* __restrict__ table4,  // [225*16]
                 float4*       __restrict__ out)     // [ROWS*64]
{
    // ---- stage table into shared memory (one-time per block) ----
    for (int i = threadIdx.x; i < TABLE_F4; i += blockDim.x)
        s_tab[i] = table4[i];
    __syncthreads();

    const int tid    = blockIdx.x * blockDim.x + threadIdx.x;
    const int stride = gridDim.x * blockDim.x;
    const float4 z = make_float4(0.f, 0.f, 0.f, 0.f);

    for (int w = tid; w < WORK; w += stride) {
        const int row = w >> 3;         // output row
        const int j   = w & 7;          // 32B lane within each coord block
        const int j2  = j * 2;          // float4 index pair base

        const int    o = __ldg(obj + row);
        const float4 f = __ldg(frac4 + row);

        float4* base = out + row * 64 + j2;   // + c*16 per coord

        if (o == 1) {
            {   // coord 0
                const float4* r = s_tab + clamp_idx(f.x) * 16 + j2;
                st256(base +  0, r[0], r[1]);
            }
            {   // coord 1
                const float4* r = s_tab + clamp_idx(f.y) * 16 + j2;
                st256(base + 16, r[0], r[1]);
            }
            {   // coord 2
                const float4* r = s_tab + clamp_idx(f.z) * 16 + j2;
                st256(base + 32, r[0], r[1]);
            }
            {   // coord 3
                const float4* r = s_tab + clamp_idx(f.w) * 16 + j2;
                st256(base + 48, r[0], r[1]);
            }
        } else {
            st256(base +  0, z, z);
            st256(base + 16, z, z);
            st256(base + 32, z, z);
            st256(base + 48, z, z);
        }
    }
}

extern "C" void kernel_launch(void* const* d_in, const int* in_sizes, int n_in,
                              void* d_out, int out_size)
{
    const float4* frac4 = (const float4*)d_in[0];   // [2048,128,4] f32
    const int*    obj   = (const int*)d_in[1];      // [2048,128] i32
    const float4* table = (const float4*)d_in[2];   // [225,64] f32
    float4* out = (float4*)d_out;

    const int smem_bytes = TABLE_F4 * sizeof(float4);   // 57600
    cudaFuncSetAttribute(roibridge_kernel,
                         cudaFuncAttributeMaxDynamicSharedMemorySize, smem_bytes);

    const int threads = 512;
    const int blocks = 152 * 3;   // 152 SMs, 3 blocks/SM

    roibridge_kernel<<<blocks, threads, smem_bytes>>>(frac4, obj, table, out);
}